// round 12
// baseline (speedup 1.0000x reference)
#include <cuda_runtime.h>
#include <cuda_bf16.h>
#include <cstdint>

// ---- model constants ----
constexpr int Bb = 32, Tt = 128, Dd = 128, Hh = 8, HDh = 16, Ll = 4;
constexpr int Vv = 50257;
constexpr int BT = Bb * Tt;           // 4096
constexpr int VP = 50304;             // V padded to multiple of 128

// ---- scratch ----
__device__ float g_x  [BT * Dd];                 // residual stream fp32
__device__ float g_h  [BT * Dd];                 // final LN fp32 (rownll)
__device__ float g_qkv[BT * 3 * Dd];
__device__ float g_nll[BT];
__device__ float g_rowsum[BT];
__device__ __align__(16) __nv_bfloat16 g_lmwb[(size_t)VP * 256];   // lm W [n][hi|lo]
__device__ __align__(16) __nv_bfloat16 g_hb[(size_t)BT * 256];     // A operand [r][hi|lo]
__device__ __align__(16) __nv_bfloat16 g_wqkh[Ll * 384 * 256];     // [l][n][hi|lo]
__device__ __align__(16) __nv_bfloat16 g_wprh[Ll * 128 * 256];
__device__ __align__(16) __nv_bfloat16 g_w1h [Ll * 512 * 256];
__device__ __align__(16) __nv_bfloat16 g_w2h [Ll * 128 * 4 * 256]; // [l][n][kc][256]
__device__ __align__(16) __nv_bfloat16 g_mlphl[4 * BT * 256];      // [kc][r][hi|lo]

__device__ __forceinline__ uint32_t smem_u32(const void* p) {
    uint32_t a;
    asm("{ .reg .u64 t; cvta.to.shared.u64 t, %1; cvt.u32.u64 %0, t; }" : "=r"(a) : "l"(p));
    return a;
}
__device__ __forceinline__ void f2hl(float v, __nv_bfloat16& hi, __nv_bfloat16& lo) {
    hi = __float2bfloat16(v);
    lo = __float2bfloat16(v - __bfloat162float(hi));
}

constexpr int LMS = 264;  // bf16 row stride for ldmatrix tiles

// ======================= HMMA core (round-4 proven) =======================
__device__ __forceinline__ void hmma_tile(const uint32_t a_base[2], const uint32_t b_base[4],
                                          float acc[2][4][4]) {
    #pragma unroll
    for (int p = 0; p < 3; p++) {
        int ka = (p == 1) ? 256 : 0;
        int kb = (p == 2) ? 256 : 0;
        #pragma unroll
        for (int ks = 0; ks < 8; ks++) {
            int ofA = ka + ks * 32;
            int ofB = kb + ks * 32;
            uint32_t a[2][4], b[4][2];
            #pragma unroll
            for (int i = 0; i < 2; i++)
                asm volatile("ldmatrix.sync.aligned.m8n8.x4.shared.b16 {%0,%1,%2,%3}, [%4];"
                             : "=r"(a[i][0]), "=r"(a[i][1]), "=r"(a[i][2]), "=r"(a[i][3])
                             : "r"(a_base[i] + ofA));
            #pragma unroll
            for (int j = 0; j < 4; j++)
                asm volatile("ldmatrix.sync.aligned.m8n8.x2.shared.b16 {%0,%1}, [%2];"
                             : "=r"(b[j][0]), "=r"(b[j][1])
                             : "r"(b_base[j] + ofB));
            #pragma unroll
            for (int i = 0; i < 2; i++)
                #pragma unroll
                for (int j = 0; j < 4; j++)
                    asm volatile(
                        "mma.sync.aligned.m16n8k16.row.col.f32.bf16.bf16.f32 "
                        "{%0,%1,%2,%3}, {%4,%5,%6,%7}, {%8,%9}, {%0,%1,%2,%3};"
                        : "+f"(acc[i][j][0]), "+f"(acc[i][j][1]),
                          "+f"(acc[i][j][2]), "+f"(acc[i][j][3])
                        : "r"(a[i][0]), "r"(a[i][1]), "r"(a[i][2]), "r"(a[i][3]),
                          "r"(b[j][0]), "r"(b[j][1]));
        }
    }
}

// ======================= weight conversion =======================
__global__ void wconv_kernel(const float* __restrict__ wq, const float* __restrict__ wk,
                             const float* __restrict__ wv, const float* __restrict__ wproj,
                             const float* __restrict__ w1, const float* __restrict__ w2) {
    int i = blockIdx.x * 256 + threadIdx.x;
    int m = blockIdx.y;
    if (m == 0 && i < BT) g_rowsum[i] = 0.f;
    if (m < 3) {
        if (i >= Ll * Hh * Dd * HDh) return;
        const float* src = (m == 0) ? wq : (m == 1) ? wk : wv;
        int e = i & 15, d = (i >> 4) & 127, h = (i >> 11) & 7, l = i >> 14;
        int n = m * 128 + h * 16 + e;
        __nv_bfloat16 hi, lo; f2hl(src[i], hi, lo);
        size_t base = ((size_t)l * 384 + n) * 256;
        g_wqkh[base + d] = hi; g_wqkh[base + 128 + d] = lo;
    } else if (m == 3) {
        if (i >= Ll * Dd * Dd) return;
        int n = i & 127, d = (i >> 7) & 127, l = i >> 14;
        __nv_bfloat16 hi, lo; f2hl(wproj[i], hi, lo);
        size_t base = ((size_t)l * 128 + n) * 256;
        g_wprh[base + d] = hi; g_wprh[base + 128 + d] = lo;
    } else if (m == 4) {
        if (i >= Ll * Dd * 512) return;
        int n = i & 511, d = (i >> 9) & 127, l = i >> 16;
        __nv_bfloat16 hi, lo; f2hl(w1[i], hi, lo);
        size_t base = ((size_t)l * 512 + n) * 256;
        g_w1h[base + d] = hi; g_w1h[base + 128 + d] = lo;
    } else {
        if (i >= Ll * 512 * Dd) return;
        int n = i & 127, k = (i >> 7) & 511, l = i >> 16;
        int kc = k >> 7, ck = k & 127;
        __nv_bfloat16 hi, lo; f2hl(w2[i], hi, lo);
        size_t base = (((size_t)l * 128 + n) * 4 + kc) * 256;
        g_w2h[base + ck] = hi; g_w2h[base + 128 + ck] = lo;
    }
}

__global__ void convw_kernel(const float* __restrict__ lm_w) {
    __shared__ float t[32][33];
    int nb = blockIdx.x * 32, kb = blockIdx.y * 32;
    int tx = threadIdx.x, ty = threadIdx.y;
    #pragma unroll
    for (int i = 0; i < 4; i++) {
        int k = kb + ty + 8 * i, n = nb + tx;
        t[ty + 8 * i][tx] = (n < Vv) ? lm_w[(size_t)k * Vv + n] : 0.f;
    }
    __syncthreads();
    #pragma unroll
    for (int i = 0; i < 4; i++) {
        int n = nb + ty + 8 * i, k = kb + tx;
        __nv_bfloat16 hi, lo; f2hl(t[tx][ty + 8 * i], hi, lo);
        size_t base = (size_t)n * 256;
        g_lmwb[base + k] = hi; g_lmwb[base + 128 + k] = lo;
    }
}

__global__ void embed_kernel(const int* __restrict__ idx,
                             const float* __restrict__ tok,
                             const float* __restrict__ pos) {
    int bt = blockIdx.x, d = threadIdx.x;
    int t = bt & (Tt - 1);
    g_x[bt * Dd + d] = tok[(size_t)idx[bt] * Dd + d] + pos[t * Dd + d];
}

// ---- LN: g_x -> g_hb (hi/lo); optionally also g_h fp32. 8 rows/block. ----
__global__ void ln_hl_kernel(const float* __restrict__ g, const float* __restrict__ b,
                             int write_f32) {
    int wid = threadIdx.x >> 5, lane = threadIdx.x & 31;
    int row = blockIdx.x * 8 + wid;
    float v[4], s = 0.f, s2 = 0.f;
    #pragma unroll
    for (int i = 0; i < 4; i++) {
        v[i] = g_x[row * Dd + lane + 32 * i];
        s += v[i]; s2 += v[i] * v[i];
    }
    #pragma unroll
    for (int o = 16; o; o >>= 1) {
        s  += __shfl_xor_sync(0xffffffffu, s,  o);
        s2 += __shfl_xor_sync(0xffffffffu, s2, o);
    }
    float mean = s * (1.f / 128.f);
    float var  = s2 * (1.f / 128.f) - mean * mean;
    float inv  = rsqrtf(var + 1e-5f);
    #pragma unroll
    for (int i = 0; i < 4; i++) {
        int d = lane + 32 * i;
        float o = (v[i] - mean) * inv * g[d] + b[d];
        __nv_bfloat16 hi, lo; f2hl(o, hi, lo);
        g_hb[(size_t)row * 256 + d] = hi;
        g_hb[(size_t)row * 256 + 128 + d] = lo;
        if (write_f32) g_h[(size_t)row * Dd + d] = o;
    }
}

// ======================= body GEMM (HMMA) =======================
// Device-symbol pointers resolved IN DEVICE CODE via selectors (host cannot pass them).
// asel: 0 = g_hb, 1 = g_mlphl.  bwsel: 0 = g_wqkh, 1 = g_wprh, 2 = g_w1h, 3 = g_w2h.
// mode 0: fp32 -> g_qkv (ld 384). mode 1: g_x += acc + bias. mode 2: relu -> g_mlphl hi/lo.
__global__ __launch_bounds__(256, 2)
void body_hmma(int asel, int bwsel, size_t bofs, int nkc, int bld,
               const float* __restrict__ bias, int mode) {
    extern __shared__ __nv_bfloat16 sm[];
    __nv_bfloat16* As = sm;               // 128 x LMS
    __nv_bfloat16* Bs = sm + 128 * LMS;   // 64 x LMS
    const __nv_bfloat16* Asrc = asel ? g_mlphl : g_hb;
    const size_t achs = asel ? (size_t)BT * 256 : 0;
    const __nv_bfloat16* Bsrc =
        (bwsel == 0) ? (g_wqkh + bofs) :
        (bwsel == 1) ? (g_wprh + bofs) :
        (bwsel == 2) ? (g_w1h + bofs) : (g_w2h + bofs);

    int tid = threadIdx.x;
    int m0 = blockIdx.x * 128, n0 = blockIdx.y * 64;
    int wid = tid >> 5, lane = tid & 31;
    int wm = (wid & 3) * 32, wn = (wid >> 2) * 32;

    uint32_t a_base[2], b_base[4];
    #pragma unroll
    for (int i = 0; i < 2; i++) {
        int row = wm + i * 16 + (lane & 15);
        int col = (lane >> 4) * 8;
        a_base[i] = smem_u32(&As[row * LMS + col]);
    }
    #pragma unroll
    for (int j = 0; j < 4; j++) {
        int row = wn + j * 8 + (lane & 7);
        int col = ((lane >> 3) & 1) * 8;
        b_base[j] = smem_u32(&Bs[row * LMS + col]);
    }

    float acc[2][4][4];
    #pragma unroll
    for (int i = 0; i < 2; i++)
        #pragma unroll
        for (int j = 0; j < 4; j++)
            #pragma unroll
            for (int q = 0; q < 4; q++) acc[i][j][q] = 0.f;

    for (int kc = 0; kc < nkc; kc++) {
        if (kc) __syncthreads();
        #pragma unroll
        for (int i = 0; i < 16; i++) {
            int idx = tid + i * 256;
            int r = idx >> 5, u = idx & 31;
            uint4 v = *(const uint4*)&Asrc[achs * kc + ((size_t)(m0 + r)) * 256 + u * 8];
            *(uint4*)&As[r * LMS + u * 8] = v;
        }
        #pragma unroll
        for (int i = 0; i < 8; i++) {
            int idx = tid + i * 256;
            int r = idx >> 5, u = idx & 31;
            uint4 v = *(const uint4*)&Bsrc[(size_t)(n0 + r) * bld + kc * 256 + u * 8];
            *(uint4*)&Bs[r * LMS + u * 8] = v;
        }
        __syncthreads();
        hmma_tile(a_base, b_base, acc);
    }

    #pragma unroll
    for (int i = 0; i < 2; i++)
        #pragma unroll
        for (int hf = 0; hf < 2; hf++) {
            int row = m0 + wm + i * 16 + (lane >> 2) + hf * 8;
            #pragma unroll
            for (int j = 0; j < 4; j++) {
                int gc = n0 + wn + j * 8 + (lane & 3) * 2;
                float v0 = acc[i][j][hf * 2];
                float v1 = acc[i][j][hf * 2 + 1];
                if (bias) { v0 += bias[gc]; v1 += bias[gc + 1]; }
                if (mode == 0) {
                    g_qkv[(size_t)row * 384 + gc]     = v0;
                    g_qkv[(size_t)row * 384 + gc + 1] = v1;
                } else if (mode == 1) {
                    g_x[(size_t)row * Dd + gc]     += v0;
                    g_x[(size_t)row * Dd + gc + 1] += v1;
                } else {
                    v0 = fmaxf(v0, 0.f); v1 = fmaxf(v1, 0.f);
                    #pragma unroll
                    for (int q = 0; q < 2; q++) {
                        float vv = q ? v1 : v0;
                        int gcq = gc + q;
                        int ckc = gcq >> 7, ck = gcq & 127;
                        __nv_bfloat16 hi, lo; f2hl(vv, hi, lo);
                        size_t dst = ((size_t)ckc * BT + row) * 256 + ck;
                        g_mlphl[dst] = hi; g_mlphl[dst + 128] = lo;
                    }
                }
            }
        }
}

// ======================= attention (writes hi/lo to g_hb) =======================
__global__ void attn_kernel() {
    __shared__ float k_s[16][129];
    __shared__ float v_s[16][129];
    __shared__ float p_s[4][128];
    int bh = blockIdx.x;
    int b = bh >> 3, h = bh & 7;
    int tid = threadIdx.x;
    int w = tid >> 5, lane = tid & 31;
    int base_bt = b * Tt;
    for (int i = tid; i < Tt * HDh; i += 128) {
        int s = i >> 4, e = i & 15;
        size_t g = (size_t)(base_bt + s) * 384 + h * HDh + e;
        k_s[e][s] = g_qkv[g + 128];
        v_s[e][s] = g_qkv[g + 256];
    }
    __syncthreads();
    const float scale = 0.08838834764831845f;
    for (int t = w; t < Tt; t += 4) {
        float q[16];
        size_t qg = (size_t)(base_bt + t) * 384 + h * HDh;
        #pragma unroll
        for (int e = 0; e < 16; e++) q[e] = g_qkv[qg + e];
        float sc[4];
        #pragma unroll
        for (int j = 0; j < 4; j++) {
            int s = lane + 32 * j;
            float dot = 0.f;
            #pragma unroll
            for (int e = 0; e < 16; e++) dot += q[e] * k_s[e][s];
            sc[j] = (s <= t) ? dot * scale : -1e30f;
        }
        float m = fmaxf(fmaxf(sc[0], sc[1]), fmaxf(sc[2], sc[3]));
        #pragma unroll
        for (int o = 16; o; o >>= 1) m = fmaxf(m, __shfl_xor_sync(0xffffffffu, m, o));
        float p[4], ps = 0.f;
        #pragma unroll
        for (int j = 0; j < 4; j++) {
            int s = lane + 32 * j;
            p[j] = (s <= t) ? __expf(sc[j] - m) : 0.f;
            ps += p[j];
        }
        #pragma unroll
        for (int o = 16; o; o >>= 1) ps += __shfl_xor_sync(0xffffffffu, ps, o);
        float inv = 1.f / ps;
        #pragma unroll
        for (int j = 0; j < 4; j++) p_s[w][lane + 32 * j] = p[j] * inv;
        __syncwarp();
        int e = lane & 15, half = lane >> 4;
        float acc = 0.f;
        int sb = half * 64;
        #pragma unroll
        for (int s = 0; s < 64; s++) acc += p_s[w][sb + s] * v_s[e][sb + s];
        acc += __shfl_xor_sync(0xffffffffu, acc, 16);
        if (lane < 16) {
            __nv_bfloat16 hi, lo; f2hl(acc, hi, lo);
            size_t ro = (size_t)(base_bt + t) * 256 + h * HDh + e;
            g_hb[ro] = hi;
            g_hb[ro + 128] = lo;
        }
        __syncwarp();
    }
}

// ======================= LM head (round-4 exact) =======================
__global__ __launch_bounds__(256, 2)
void lmhead_hmma(const float* __restrict__ lmb, float* __restrict__ out) {
    extern __shared__ __nv_bfloat16 sm[];
    __nv_bfloat16* As = sm;
    __nv_bfloat16* Bs = sm + 128 * LMS;
    int tid = threadIdx.x;
    int m0 = blockIdx.x * 128, n0 = blockIdx.y * 64;

    #pragma unroll
    for (int i = 0; i < 16; i++) {
        int idx = tid + i * 256;
        int r = idx >> 5, u = idx & 31;
        uint4 v = *(const uint4*)&g_hb[((size_t)(m0 + r)) * 256 + u * 8];
        *(uint4*)&As[r * LMS + u * 8] = v;
    }
    #pragma unroll
    for (int i = 0; i < 8; i++) {
        int idx = tid + i * 256;
        int r = idx >> 5, u = idx & 31;
        uint4 v = *(const uint4*)&g_lmwb[((size_t)(n0 + r)) * 256 + u * 8];
        *(uint4*)&Bs[r * LMS + u * 8] = v;
    }
    __syncthreads();

    int wid = tid >> 5, lane = tid & 31;
    int wm = (wid & 3) * 32;
    int wn = (wid >> 2) * 32;

    uint32_t a_base[2], b_base[4];
    #pragma unroll
    for (int i = 0; i < 2; i++) {
        int row = wm + i * 16 + (lane & 15);
        int col = (lane >> 4) * 8;
        a_base[i] = smem_u32(&As[row * LMS + col]);
    }
    #pragma unroll
    for (int j = 0; j < 4; j++) {
        int row = wn + j * 8 + (lane & 7);
        int col = ((lane >> 3) & 1) * 8;
        b_base[j] = smem_u32(&Bs[row * LMS + col]);
    }

    float acc[2][4][4];
    #pragma unroll
    for (int i = 0; i < 2; i++)
        #pragma unroll
        for (int j = 0; j < 4; j++)
            #pragma unroll
            for (int q = 0; q < 4; q++) acc[i][j][q] = 0.f;
    hmma_tile(a_base, b_base, acc);

    float bias0[4], bias1[4];
    #pragma unroll
    for (int j = 0; j < 4; j++) {
        int c = n0 + wn + j * 8 + (lane & 3) * 2;
        bias0[j] = (c < Vv) ? lmb[c] : 0.f;
        bias1[j] = (c + 1 < Vv) ? lmb[c + 1] : 0.f;
    }

    #pragma unroll
    for (int i = 0; i < 2; i++) {
        #pragma unroll
        for (int hf = 0; hf < 2; hf++) {
            int row = m0 + wm + i * 16 + (lane >> 2) + hf * 8;
            size_t ro = (size_t)row * Vv;
            float rexp = 0.f;
            #pragma unroll
            for (int j = 0; j < 4; j++) {
                int c = n0 + wn + j * 8 + (lane & 3) * 2;
                float v0 = acc[i][j][hf * 2]     + bias0[j];
                float v1 = acc[i][j][hf * 2 + 1] + bias1[j];
                if (c < Vv) {
                    if (out) out[ro + c] = v0;
                    rexp += __expf(v0);
                }
                if (c + 1 < Vv) {
                    if (out) out[ro + c + 1] = v1;
                    rexp += __expf(v1);
                }
            }
            rexp += __shfl_xor_sync(0xffffffffu, rexp, 1);
            rexp += __shfl_xor_sync(0xffffffffu, rexp, 2);
            if ((lane & 3) == 0) atomicAdd(&g_rowsum[row], rexp);
        }
    }
}

// ======================= loss =======================
__global__ void rownll_kernel(const int* __restrict__ targets,
                              const float* __restrict__ lm_w,
                              const float* __restrict__ lmb) {
    int gw = (blockIdx.x * blockDim.x + threadIdx.x) >> 5;
    int lane = threadIdx.x & 31;
    for (int r = gw; r < BT; r += 512) {
        int tgt = targets[r];
        float dot = 0.f;
        const float* xr = &g_h[(size_t)r * Dd];
        #pragma unroll
        for (int i = 0; i < 4; i++) {
            int d = lane + 32 * i;
            dot += xr[d] * lm_w[(size_t)d * Vv + tgt];
        }
        #pragma unroll
        for (int o = 16; o; o >>= 1) dot += __shfl_xor_sync(0xffffffffu, dot, o);
        if (lane == 0) g_nll[r] = logf(g_rowsum[r]) - (dot + lmb[tgt]);
    }
}

__global__ void lossred_kernel(float* __restrict__ loss_out) {
    int tid = threadIdx.x;
    float local = 0.f;
    for (int r = tid; r < BT; r += 1024) local += g_nll[r];
    #pragma unroll
    for (int o = 16; o; o >>= 1) local += __shfl_xor_sync(0xffffffffu, local, o);
    __shared__ float red[32];
    if ((tid & 31) == 0) red[tid >> 5] = local;
    __syncthreads();
    if (tid < 32) {
        float v = red[tid];
        #pragma unroll
        for (int o = 16; o; o >>= 1) v += __shfl_xor_sync(0xffffffffu, v, o);
        if (tid == 0 && loss_out) *loss_out = v * (1.f / (float)BT);
    }
}

// ======================= launch =======================
extern "C" void kernel_launch(void* const* d_in, const int* in_sizes, int n_in,
                              void* d_out, int out_size) {
    const int*   idx     = (const int*)  d_in[0];
    const int*   targets = (const int*)  d_in[1];
    const float* tok_emb = (const float*)d_in[2];
    const float* pos_emb = (const float*)d_in[3];
    const float* wq      = (const float*)d_in[4];
    const float* wk      = (const float*)d_in[5];
    const float* wv      = (const float*)d_in[6];
    const float* wproj   = (const float*)d_in[7];
    const float* bproj   = (const float*)d_in[8];
    const float* w1      = (const float*)d_in[9];
    const float* b1      = (const float*)d_in[10];
    const float* w2      = (const float*)d_in[11];
    const float* b2      = (const float*)d_in[12];
    const float* ln1_g   = (const float*)d_in[13];
    const float* ln1_b   = (const float*)d_in[14];
    const float* ln2_g   = (const float*)d_in[15];
    const float* ln2_b   = (const float*)d_in[16];
    const float* lnf_g   = (const float*)d_in[17];
    const float* lnf_b   = (const float*)d_in[18];
    const float* lm_w    = (const float*)d_in[19];
    const float* lm_b    = (const float*)d_in[20];

    float* outf = (float*)d_out;
    long long btv = (long long)BT * Vv;
    float* logits = ((long long)out_size >= btv) ? outf : nullptr;
    float* lossp  = nullptr;
    if ((long long)out_size == btv + 1) lossp = outf + btv;
    else if ((long long)out_size < btv && out_size >= 1) lossp = outf + (out_size - 1);

    constexpr int SMEM_HMMA = (128 * LMS + 64 * LMS) * 2;  // 101376
    cudaFuncSetAttribute(lmhead_hmma, cudaFuncAttributeMaxDynamicSharedMemorySize, SMEM_HMMA);
    cudaFuncSetAttribute(body_hmma,   cudaFuncAttributeMaxDynamicSharedMemorySize, SMEM_HMMA);

    wconv_kernel<<<dim3(1024, 6), 256>>>(wq, wk, wv, wproj, w1, w2);
    convw_kernel<<<dim3(VP / 32, 4), dim3(32, 8)>>>(lm_w);
    embed_kernel<<<BT, 128>>>(idx, tok_emb, pos_emb);

    for (int l = 0; l < Ll; l++) {
        ln_hl_kernel<<<BT / 8, 256>>>(ln1_g + l * Dd, ln1_b + l * Dd, 0);
        // qkv = hb @ wqkh[l] -> g_qkv fp32 (no bias)
        body_hmma<<<dim3(BT / 128, 6), 256, SMEM_HMMA>>>(
            0, 0, (size_t)l * 384 * 256, 1, 256, nullptr, 0);
        attn_kernel<<<Bb * Hh, 128>>>();
        // x += attn_out @ wproj + bproj
        body_hmma<<<dim3(BT / 128, 2), 256, SMEM_HMMA>>>(
            0, 1, (size_t)l * 128 * 256, 1, 256, bproj + l * Dd, 1);
        ln_hl_kernel<<<BT / 8, 256>>>(ln2_g + l * Dd, ln2_b + l * Dd, 0);
        // mlp1 = relu(hb @ w1 + b1) -> g_mlphl
        body_hmma<<<dim3(BT / 128, 8), 256, SMEM_HMMA>>>(
            0, 2, (size_t)l * 512 * 256, 1, 256, b1 + l * 4 * Dd, 2);
        // x += mlp1 @ w2 + b2
        body_hmma<<<dim3(BT / 128, 2), 256, SMEM_HMMA>>>(
            1, 3, (size_t)l * 128 * 4 * 256, 4, 1024, b2 + l * Dd, 1);
    }
    ln_hl_kernel<<<BT / 8, 256>>>(lnf_g, lnf_b, 1);
    lmhead_hmma<<<dim3(BT / 128, VP / 64), 256, SMEM_HMMA>>>(lm_b, logits);
    rownll_kernel<<<64, 256>>>(targets, lm_w, lm_b);
    lossred_kernel<<<1, 1024>>>(lossp);
}

// round 15
// speedup vs baseline: 1.4290x; 1.4290x over previous
#include <cuda_runtime.h>
#include <cuda_bf16.h>
#include <cuda_fp16.h>
#include <cstdint>

// ---- model constants ----
constexpr int Bb = 32, Tt = 128, Dd = 128, Hh = 8, HDh = 16, Ll = 4;
constexpr int Vv = 50257;
constexpr int BT = Bb * Tt;           // 4096
constexpr int VP = 50304;             // V padded to multiple of 128

// ---- scratch (static device globals; no allocation allowed) ----
__device__ float g_x  [BT * Dd];
__device__ float g_h  [BT * Dd];
__device__ float g_qkv[BT * 3 * Dd];
__device__ float g_att[BT * Dd];      // reused as per-row nll scratch at the end
__device__ float g_mlp[BT * 4 * Dd];
__device__ float g_wqkv[Ll * Dd * 3 * Dd];
__device__ float g_rowsum[BT];        // holds sum(exp(logit)) * 2^-8
__device__ __align__(16) __nv_bfloat16 g_lmwb[(size_t)VP * 256];  // [n][0:128]=hi,[128:256]=lo
__device__ __align__(16) __nv_bfloat16 g_hb[(size_t)BT * 256];    // [r][0:128]=hi,[128:256]=lo

__device__ __forceinline__ float* buf_sel(int s) {
    switch (s) {
        case 0: return g_x;
        case 1: return g_h;
        case 2: return g_qkv;
        case 3: return g_att;
        default: return g_mlp;
    }
}

__device__ __forceinline__ uint32_t smem_u32(const void* p) {
    uint32_t a;
    asm("{ .reg .u64 t; cvta.to.shared.u64 t, %1; cvt.u32.u64 %0, t; }" : "=r"(a) : "l"(p));
    return a;
}

// ======================= small prep kernels =======================
__global__ void prep_kernel(const float* __restrict__ wq,
                            const float* __restrict__ wk,
                            const float* __restrict__ wv) {
    int i = blockIdx.x * blockDim.x + threadIdx.x;
    if (i < BT) g_rowsum[i] = 0.f;
    if (i < Ll * Hh * Dd * HDh) {
        int e = i & 15;
        int d = (i >> 4) & 127;
        int h = (i >> 11) & 7;
        int l = i >> 14;
        int dst = (l * Dd + d) * 384 + h * HDh + e;
        g_wqkv[dst]       = wq[i];
        g_wqkv[dst + 128] = wk[i];
        g_wqkv[dst + 256] = wv[i];
    }
}

// lm_w [128][Vv] -> g_lmwb [VP][256] bf16 hi|lo (transposed, zero-padded)
__global__ void convw_kernel(const float* __restrict__ lm_w) {
    __shared__ float t[32][33];
    int nb = blockIdx.x * 32, kb = blockIdx.y * 32;
    int tx = threadIdx.x, ty = threadIdx.y;
    #pragma unroll
    for (int i = 0; i < 4; i++) {
        int k = kb + ty + 8 * i, n = nb + tx;
        t[ty + 8 * i][tx] = (n < Vv) ? lm_w[(size_t)k * Vv + n] : 0.f;
    }
    __syncthreads();
    #pragma unroll
    for (int i = 0; i < 4; i++) {
        int n = nb + ty + 8 * i, k = kb + tx;
        float v = t[tx][ty + 8 * i];
        __nv_bfloat16 hi = __float2bfloat16(v);
        __nv_bfloat16 lo = __float2bfloat16(v - __bfloat162float(hi));
        size_t base = (size_t)n * 256;
        g_lmwb[base + k]       = hi;
        g_lmwb[base + 128 + k] = lo;
    }
}

// g_h [BT][128] -> g_hb [BT][256] bf16 hi|lo
__global__ void convh_kernel() {
    int i = blockIdx.x * 256 + threadIdx.x;
    if (i >= BT * Dd) return;
    int r = i >> 7, k = i & 127;
    float v = g_h[i];
    __nv_bfloat16 hi = __float2bfloat16(v);
    __nv_bfloat16 lo = __float2bfloat16(v - __bfloat162float(hi));
    g_hb[(size_t)r * 256 + k]       = hi;
    g_hb[(size_t)r * 256 + 128 + k] = lo;
}

__global__ void embed_kernel(const int* __restrict__ idx,
                             const float* __restrict__ tok,
                             const float* __restrict__ pos) {
    int bt = blockIdx.x, d = threadIdx.x;
    int t = bt & (Tt - 1);
    g_x[bt * Dd + d] = tok[(size_t)idx[bt] * Dd + d] + pos[t * Dd + d];
}

__global__ void ln_kernel(const float* __restrict__ g, const float* __restrict__ b) {
    int row = blockIdx.x, tid = threadIdx.x;
    float v = g_x[row * Dd + tid];
    float s = v, s2 = v * v;
    #pragma unroll
    for (int o = 16; o; o >>= 1) {
        s  += __shfl_xor_sync(0xffffffffu, s,  o);
        s2 += __shfl_xor_sync(0xffffffffu, s2, o);
    }
    __shared__ float sh[8];
    int w = tid >> 5;
    if ((tid & 31) == 0) { sh[w] = s; sh[4 + w] = s2; }
    __syncthreads();
    float ts  = sh[0] + sh[1] + sh[2] + sh[3];
    float ts2 = sh[4] + sh[5] + sh[6] + sh[7];
    float mean = ts * (1.f / 128.f);
    float var  = ts2 * (1.f / 128.f) - mean * mean;
    g_h[row * Dd + tid] = (v - mean) * rsqrtf(var + 1e-5f) * g[tid] + b[tid];
}

// ======================= body GEMM (round-4 proven) =======================
__global__ __launch_bounds__(256)
void gemm64_kernel(int asel, const float* __restrict__ Bext, int bofs,
                   const float* __restrict__ bias, int use_res, int csel,
                   int N, int K, int relu) {
    __shared__ float As[32][65];
    __shared__ __align__(16) float Bs[32][64];
    const float* A = buf_sel(asel);
    float* C = buf_sel(csel);
    const float* Bm = Bext ? Bext : (g_wqkv + bofs);
    int tid = threadIdx.x;
    int tx = tid & 15, ty = tid >> 4;
    int r0 = blockIdx.y * 64, c0 = blockIdx.x * 64;
    int ar = tid >> 3, ak = (tid & 7) * 4;
    int br = tid >> 4, bc = (tid & 15) * 4;
    float acc[4][4] = {};
    for (int k0 = 0; k0 < K; k0 += 32) {
        float4 a0 = *(const float4*)&A[(size_t)(r0 + ar)      * K + k0 + ak];
        float4 a1 = *(const float4*)&A[(size_t)(r0 + ar + 32) * K + k0 + ak];
        As[ak + 0][ar] = a0.x; As[ak + 1][ar] = a0.y;
        As[ak + 2][ar] = a0.z; As[ak + 3][ar] = a0.w;
        As[ak + 0][ar + 32] = a1.x; As[ak + 1][ar + 32] = a1.y;
        As[ak + 2][ar + 32] = a1.z; As[ak + 3][ar + 32] = a1.w;
        *(float4*)&Bs[br][bc]      = *(const float4*)&Bm[(size_t)(k0 + br)      * N + c0 + bc];
        *(float4*)&Bs[br + 16][bc] = *(const float4*)&Bm[(size_t)(k0 + br + 16) * N + c0 + bc];
        __syncthreads();
        #pragma unroll
        for (int kk = 0; kk < 32; kk++) {
            float4 bv = *(const float4*)&Bs[kk][tx * 4];
            float a0r = As[kk][ty * 4 + 0];
            float a1r = As[kk][ty * 4 + 1];
            float a2r = As[kk][ty * 4 + 2];
            float a3r = As[kk][ty * 4 + 3];
            acc[0][0] += a0r * bv.x; acc[0][1] += a0r * bv.y; acc[0][2] += a0r * bv.z; acc[0][3] += a0r * bv.w;
            acc[1][0] += a1r * bv.x; acc[1][1] += a1r * bv.y; acc[1][2] += a1r * bv.z; acc[1][3] += a1r * bv.w;
            acc[2][0] += a2r * bv.x; acc[2][1] += a2r * bv.y; acc[2][2] += a2r * bv.z; acc[2][3] += a2r * bv.w;
            acc[3][0] += a3r * bv.x; acc[3][1] += a3r * bv.y; acc[3][2] += a3r * bv.z; acc[3][3] += a3r * bv.w;
        }
        __syncthreads();
    }
    #pragma unroll
    for (int i = 0; i < 4; i++) {
        int rr = r0 + ty * 4 + i;
        #pragma unroll
        for (int j = 0; j < 4; j++) {
            int cc = c0 + tx * 4 + j;
            float v = acc[i][j];
            if (bias) v += bias[cc];
            if (relu) v = fmaxf(v, 0.f);
            if (use_res) v += g_x[(size_t)rr * N + cc];
            C[(size_t)rr * N + cc] = v;
        }
    }
}

// ======================= attention (round-4 proven) =======================
__global__ void attn_kernel() {
    __shared__ float k_s[16][129];
    __shared__ float v_s[16][129];
    __shared__ float p_s[4][128];
    int bh = blockIdx.x;
    int b = bh >> 3, h = bh & 7;
    int tid = threadIdx.x;
    int w = tid >> 5, lane = tid & 31;
    int base_bt = b * Tt;
    for (int i = tid; i < Tt * HDh; i += 128) {
        int s = i >> 4, e = i & 15;
        size_t g = (size_t)(base_bt + s) * 384 + h * HDh + e;
        k_s[e][s] = g_qkv[g + 128];
        v_s[e][s] = g_qkv[g + 256];
    }
    __syncthreads();
    const float scale = 0.08838834764831845f;
    for (int t = w; t < Tt; t += 4) {
        float q[16];
        size_t qg = (size_t)(base_bt + t) * 384 + h * HDh;
        #pragma unroll
        for (int e = 0; e < 16; e++) q[e] = g_qkv[qg + e];
        float sc[4];
        #pragma unroll
        for (int j = 0; j < 4; j++) {
            int s = lane + 32 * j;
            float dot = 0.f;
            #pragma unroll
            for (int e = 0; e < 16; e++) dot += q[e] * k_s[e][s];
            sc[j] = (s <= t) ? dot * scale : -1e30f;
        }
        float m = fmaxf(fmaxf(sc[0], sc[1]), fmaxf(sc[2], sc[3]));
        #pragma unroll
        for (int o = 16; o; o >>= 1) m = fmaxf(m, __shfl_xor_sync(0xffffffffu, m, o));
        float p[4], ps = 0.f;
        #pragma unroll
        for (int j = 0; j < 4; j++) {
            int s = lane + 32 * j;
            p[j] = (s <= t) ? __expf(sc[j] - m) : 0.f;
            ps += p[j];
        }
        #pragma unroll
        for (int o = 16; o; o >>= 1) ps += __shfl_xor_sync(0xffffffffu, ps, o);
        float inv = 1.f / ps;
        #pragma unroll
        for (int j = 0; j < 4; j++) p_s[w][lane + 32 * j] = p[j] * inv;
        __syncwarp();
        int e = lane & 15, half = lane >> 4;
        float acc = 0.f;
        int sb = half * 64;
        #pragma unroll
        for (int s = 0; s < 64; s++) acc += p_s[w][sb + s] * v_s[e][sb + s];
        acc += __shfl_xor_sync(0xffffffffu, acc, 16);
        if (lane < 16) g_att[(size_t)(base_bt + t) * Dd + h * HDh + e] = acc;
        __syncwarp();
    }
}

// ======================= LM head (HMMA; f16x2 MUFU-halved exp epilogue) =======================
constexpr int LMS = 264;  // row stride in bf16 elems

__global__ __launch_bounds__(256, 2)
void lmhead_hmma(const float* __restrict__ lmb, float* __restrict__ out) {
    extern __shared__ __nv_bfloat16 sm[];
    __nv_bfloat16* As = sm;               // 128 x LMS
    __nv_bfloat16* Bs = sm + 128 * LMS;   // 64 x LMS
    int tid = threadIdx.x;
    int m0 = blockIdx.x * 128, n0 = blockIdx.y * 64;

    #pragma unroll
    for (int i = 0; i < 16; i++) {
        int idx = tid + i * 256;
        int r = idx >> 5, u = idx & 31;
        uint4 v = *(const uint4*)&g_hb[((size_t)(m0 + r)) * 256 + u * 8];
        *(uint4*)&As[r * LMS + u * 8] = v;
    }
    #pragma unroll
    for (int i = 0; i < 8; i++) {
        int idx = tid + i * 256;
        int r = idx >> 5, u = idx & 31;
        uint4 v = *(const uint4*)&g_lmwb[((size_t)(n0 + r)) * 256 + u * 8];
        *(uint4*)&Bs[r * LMS + u * 8] = v;
    }
    __syncthreads();

    int wid = tid >> 5, lane = tid & 31;
    int wm = (wid & 3) * 32;
    int wn = (wid >> 2) * 32;

    uint32_t a_base[2], b_base[4];
    #pragma unroll
    for (int i = 0; i < 2; i++) {
        int row = wm + i * 16 + (lane & 15);
        int col = (lane >> 4) * 8;
        a_base[i] = smem_u32(&As[row * LMS + col]);
    }
    #pragma unroll
    for (int j = 0; j < 4; j++) {
        int row = wn + j * 8 + (lane & 7);
        int col = ((lane >> 3) & 1) * 8;
        b_base[j] = smem_u32(&Bs[row * LMS + col]);
    }

    float acc[2][4][4];
    #pragma unroll
    for (int i = 0; i < 2; i++)
        #pragma unroll
        for (int j = 0; j < 4; j++)
            #pragma unroll
            for (int q = 0; q < 4; q++) acc[i][j][q] = 0.f;

    #pragma unroll
    for (int p = 0; p < 3; p++) {
        int ka = (p == 1) ? 256 : 0;
        int kb = (p == 2) ? 256 : 0;
        #pragma unroll
        for (int ks = 0; ks < 8; ks++) {
            int ofA = ka + ks * 32;
            int ofB = kb + ks * 32;
            uint32_t a[2][4], b[4][2];
            #pragma unroll
            for (int i = 0; i < 2; i++)
                asm volatile("ldmatrix.sync.aligned.m8n8.x4.shared.b16 {%0,%1,%2,%3}, [%4];"
                             : "=r"(a[i][0]), "=r"(a[i][1]), "=r"(a[i][2]), "=r"(a[i][3])
                             : "r"(a_base[i] + ofA));
            #pragma unroll
            for (int j = 0; j < 4; j++)
                asm volatile("ldmatrix.sync.aligned.m8n8.x2.shared.b16 {%0,%1}, [%2];"
                             : "=r"(b[j][0]), "=r"(b[j][1])
                             : "r"(b_base[j] + ofB));
            #pragma unroll
            for (int i = 0; i < 2; i++)
                #pragma unroll
                for (int j = 0; j < 4; j++)
                    asm volatile(
                        "mma.sync.aligned.m16n8k16.row.col.f32.bf16.bf16.f32 "
                        "{%0,%1,%2,%3}, {%4,%5,%6,%7}, {%8,%9}, {%0,%1,%2,%3};"
                        : "+f"(acc[i][j][0]), "+f"(acc[i][j][1]),
                          "+f"(acc[i][j][2]), "+f"(acc[i][j][3])
                        : "r"(a[i][0]), "r"(a[i][1]), "r"(a[i][2]), "r"(a[i][3]),
                          "r"(b[j][0]), "r"(b[j][1]));
        }
    }

    float bias0[4], bias1[4];
    #pragma unroll
    for (int j = 0; j < 4; j++) {
        int c = n0 + wn + j * 8 + (lane & 3) * 2;
        bias0[j] = (c < Vv) ? lmb[c] : 0.f;
        bias1[j] = (c + 1 < Vv) ? lmb[c + 1] : 0.f;
    }

    // exp(v) = 2^(v*log2e - 8) * 2^8 ; rowsum stored scaled by 2^-8 (keeps half normal-range)
    const __half2 l2e2 = __float2half2_rn(1.4426950408889634f);
    const __half2 m8_2 = __float2half2_rn(-8.0f);
    const bool full = (n0 + 64 <= Vv);   // uniform per block

    #pragma unroll
    for (int i = 0; i < 2; i++) {
        #pragma unroll
        for (int hf = 0; hf < 2; hf++) {
            int row = m0 + wm + i * 16 + (lane >> 2) + hf * 8;
            size_t ro = (size_t)row * Vv;
            __half2 hs = __float2half2_rn(0.f);
            #pragma unroll
            for (int j = 0; j < 4; j++) {
                int c = n0 + wn + j * 8 + (lane & 3) * 2;
                float v0 = acc[i][j][hf * 2]     + bias0[j];
                float v1 = acc[i][j][hf * 2 + 1] + bias1[j];
                float e0 = v0, e1 = v1;
                if (full) {
                    if (out) { out[ro + c] = v0; out[ro + c + 1] = v1; }
                } else {
                    if (c < Vv && out) out[ro + c] = v0;
                    if (c + 1 < Vv && out) out[ro + c + 1] = v1;
                    if (c >= Vv)     e0 = -1000.f;
                    if (c + 1 >= Vv) e1 = -1000.f;
                }
                __half2 hv = __floats2half2_rn(e0, e1);
                hv = __hfma2(hv, l2e2, m8_2);
                uint32_t hvu = *reinterpret_cast<uint32_t*>(&hv);
                uint32_t eo;
                asm("ex2.approx.f16x2 %0, %1;" : "=r"(eo) : "r"(hvu));
                hs = __hadd2(hs, *reinterpret_cast<__half2*>(&eo));
            }
            float rexp = __low2float(hs) + __high2float(hs);
            rexp += __shfl_xor_sync(0xffffffffu, rexp, 1);
            rexp += __shfl_xor_sync(0xffffffffu, rexp, 2);
            if ((lane & 3) == 0) atomicAdd(&g_rowsum[row], rexp);
        }
    }
}

// ======================= loss =======================
__global__ void rownll_kernel(const int* __restrict__ targets,
                              const float* __restrict__ lm_w,
                              const float* __restrict__ lmb) {
    int gw = (blockIdx.x * blockDim.x + threadIdx.x) >> 5;
    int lane = threadIdx.x & 31;
    for (int r = gw; r < BT; r += 512) {
        int tgt = targets[r];
        float dot = 0.f;
        const float* xr = &g_h[(size_t)r * Dd];
        #pragma unroll
        for (int i = 0; i < 4; i++) {
            int d = lane + 32 * i;
            dot += xr[d] * lm_w[(size_t)d * Vv + tgt];
        }
        #pragma unroll
        for (int o = 16; o; o >>= 1) dot += __shfl_xor_sync(0xffffffffu, dot, o);
        // rowsum is scaled by 2^-8 -> add back 8*ln2
        if (lane == 0)
            g_att[r] = logf(g_rowsum[r]) + 5.545177444479562f - (dot + lmb[tgt]);
    }
}

__global__ void lossred_kernel(float* __restrict__ loss_out) {
    int tid = threadIdx.x;
    float local = 0.f;
    for (int r = tid; r < BT; r += 1024) local += g_att[r];
    #pragma unroll
    for (int o = 16; o; o >>= 1) local += __shfl_xor_sync(0xffffffffu, local, o);
    __shared__ float red[32];
    if ((tid & 31) == 0) red[tid >> 5] = local;
    __syncthreads();
    if (tid < 32) {
        float v = red[tid];
        #pragma unroll
        for (int o = 16; o; o >>= 1) v += __shfl_xor_sync(0xffffffffu, v, o);
        if (tid == 0 && loss_out) *loss_out = v * (1.f / (float)BT);
    }
}

// ======================= launch =======================
extern "C" void kernel_launch(void* const* d_in, const int* in_sizes, int n_in,
                              void* d_out, int out_size) {
    const int*   idx     = (const int*)  d_in[0];
    const int*   targets = (const int*)  d_in[1];
    const float* tok_emb = (const float*)d_in[2];
    const float* pos_emb = (const float*)d_in[3];
    const float* wq      = (const float*)d_in[4];
    const float* wk      = (const float*)d_in[5];
    const float* wv      = (const float*)d_in[6];
    const float* wproj   = (const float*)d_in[7];
    const float* bproj   = (const float*)d_in[8];
    const float* w1      = (const float*)d_in[9];
    const float* b1      = (const float*)d_in[10];
    const float* w2      = (const float*)d_in[11];
    const float* b2      = (const float*)d_in[12];
    const float* ln1_g   = (const float*)d_in[13];
    const float* ln1_b   = (const float*)d_in[14];
    const float* ln2_g   = (const float*)d_in[15];
    const float* ln2_b   = (const float*)d_in[16];
    const float* lnf_g   = (const float*)d_in[17];
    const float* lnf_b   = (const float*)d_in[18];
    const float* lm_w    = (const float*)d_in[19];
    const float* lm_b    = (const float*)d_in[20];

    float* outf = (float*)d_out;
    long long btv = (long long)BT * Vv;
    float* logits = ((long long)out_size >= btv) ? outf : nullptr;
    float* lossp  = nullptr;
    if ((long long)out_size == btv + 1) lossp = outf + btv;
    else if ((long long)out_size < btv && out_size >= 1) lossp = outf + (out_size - 1);

    constexpr int LM_SMEM = (128 * LMS + 64 * LMS) * 2;  // 101376
    cudaFuncSetAttribute(lmhead_hmma, cudaFuncAttributeMaxDynamicSharedMemorySize, LM_SMEM);

    prep_kernel<<<256, 256>>>(wq, wk, wv);
    convw_kernel<<<dim3(VP / 32, 4), dim3(32, 8)>>>(lm_w);
    embed_kernel<<<BT, 128>>>(idx, tok_emb, pos_emb);

    for (int l = 0; l < Ll; l++) {
        ln_kernel<<<BT, 128>>>(ln1_g + l * Dd, ln1_b + l * Dd);
        gemm64_kernel<<<dim3(384 / 64, BT / 64), 256>>>(
            1, nullptr, l * Dd * 384, nullptr, 0, 2, 384, 128, 0);
        attn_kernel<<<Bb * Hh, 128>>>();
        gemm64_kernel<<<dim3(128 / 64, BT / 64), 256>>>(
            3, wproj + (size_t)l * Dd * Dd, 0, bproj + l * Dd, 1, 0, 128, 128, 0);
        ln_kernel<<<BT, 128>>>(ln2_g + l * Dd, ln2_b + l * Dd);
        gemm64_kernel<<<dim3(512 / 64, BT / 64), 256>>>(
            1, w1 + (size_t)l * Dd * 4 * Dd, 0, b1 + l * 4 * Dd, 0, 4, 512, 128, 1);
        gemm64_kernel<<<dim3(128 / 64, BT / 64), 256>>>(
            4, w2 + (size_t)l * 4 * Dd * Dd, 0, b2 + l * Dd, 1, 0, 128, 512, 0);
    }
    ln_kernel<<<BT, 128>>>(lnf_g, lnf_b);
    convh_kernel<<<(BT * Dd + 255) / 256, 256>>>();
    lmhead_hmma<<<dim3(BT / 128, VP / 64), 256, LM_SMEM>>>(lm_b, logits);
    rownll_kernel<<<64, 256>>>(targets, lm_w, lm_b);
    lossred_kernel<<<1, 1024>>>(lossp);
}

// round 16
// speedup vs baseline: 1.7305x; 1.2110x over previous
#include <cuda_runtime.h>
#include <cuda_bf16.h>
#include <cstdint>

// ---- model constants ----
constexpr int Bb = 32, Tt = 128, Dd = 128, Hh = 8, HDh = 16, Ll = 4;
constexpr int Vv = 50257;
constexpr int BT = Bb * Tt;           // 4096
constexpr int VP = 50304;             // V padded to multiple of 128

// ---- scratch (static device globals; no allocation allowed) ----
__device__ float g_x  [BT * Dd];
__device__ float g_h  [BT * Dd];
__device__ float g_qkv[BT * 3 * Dd];
__device__ float g_att[BT * Dd];      // reused as per-row nll scratch at the end
__device__ float g_mlp[BT * 4 * Dd];
__device__ float g_wqkv[Ll * Dd * 3 * Dd];
__device__ float g_rowsum[BT];
__device__ __align__(16) __nv_bfloat16 g_lmwb[(size_t)VP * 256];  // [n][0:128]=hi,[128:256]=lo
__device__ __align__(16) __nv_bfloat16 g_hb[(size_t)BT * 256];    // [r][0:128]=hi,[128:256]=lo

__device__ __forceinline__ float* buf_sel(int s) {
    switch (s) {
        case 0: return g_x;
        case 1: return g_h;
        case 2: return g_qkv;
        case 3: return g_att;
        default: return g_mlp;
    }
}

__device__ __forceinline__ uint32_t smem_u32(const void* p) {
    uint32_t a;
    asm("{ .reg .u64 t; cvta.to.shared.u64 t, %1; cvt.u32.u64 %0, t; }" : "=r"(a) : "l"(p));
    return a;
}

// ======================= small prep kernels =======================
__global__ void prep_kernel(const float* __restrict__ wq,
                            const float* __restrict__ wk,
                            const float* __restrict__ wv) {
    int i = blockIdx.x * blockDim.x + threadIdx.x;
    if (i < BT) g_rowsum[i] = 0.f;
    if (i < Ll * Hh * Dd * HDh) {
        int e = i & 15;
        int d = (i >> 4) & 127;
        int h = (i >> 11) & 7;
        int l = i >> 14;
        int dst = (l * Dd + d) * 384 + h * HDh + e;
        g_wqkv[dst]       = wq[i];
        g_wqkv[dst + 128] = wk[i];
        g_wqkv[dst + 256] = wv[i];
    }
}

// lm_w [128][Vv] -> g_lmwb [VP][256] bf16 hi|lo (transposed, zero-padded)
__global__ void convw_kernel(const float* __restrict__ lm_w) {
    __shared__ float t[32][33];
    int nb = blockIdx.x * 32, kb = blockIdx.y * 32;
    int tx = threadIdx.x, ty = threadIdx.y;
    #pragma unroll
    for (int i = 0; i < 4; i++) {
        int k = kb + ty + 8 * i, n = nb + tx;
        t[ty + 8 * i][tx] = (n < Vv) ? lm_w[(size_t)k * Vv + n] : 0.f;
    }
    __syncthreads();
    #pragma unroll
    for (int i = 0; i < 4; i++) {
        int n = nb + ty + 8 * i, k = kb + tx;
        float v = t[tx][ty + 8 * i];
        __nv_bfloat16 hi = __float2bfloat16(v);
        __nv_bfloat16 lo = __float2bfloat16(v - __bfloat162float(hi));
        size_t base = (size_t)n * 256;
        g_lmwb[base + k]       = hi;
        g_lmwb[base + 128 + k] = lo;
    }
}

// g_h [BT][128] -> g_hb [BT][256] bf16 hi|lo
__global__ void convh_kernel() {
    int i = blockIdx.x * 256 + threadIdx.x;
    if (i >= BT * Dd) return;
    int r = i >> 7, k = i & 127;
    float v = g_h[i];
    __nv_bfloat16 hi = __float2bfloat16(v);
    __nv_bfloat16 lo = __float2bfloat16(v - __bfloat162float(hi));
    g_hb[(size_t)r * 256 + k]       = hi;
    g_hb[(size_t)r * 256 + 128 + k] = lo;
}

__global__ void embed_kernel(const int* __restrict__ idx,
                             const float* __restrict__ tok,
                             const float* __restrict__ pos) {
    int bt = blockIdx.x, d = threadIdx.x;
    int t = bt & (Tt - 1);
    g_x[bt * Dd + d] = tok[(size_t)idx[bt] * Dd + d] + pos[t * Dd + d];
}

__global__ void ln_kernel(const float* __restrict__ g, const float* __restrict__ b) {
    int row = blockIdx.x, tid = threadIdx.x;
    float v = g_x[row * Dd + tid];
    float s = v, s2 = v * v;
    #pragma unroll
    for (int o = 16; o; o >>= 1) {
        s  += __shfl_xor_sync(0xffffffffu, s,  o);
        s2 += __shfl_xor_sync(0xffffffffu, s2, o);
    }
    __shared__ float sh[8];
    int w = tid >> 5;
    if ((tid & 31) == 0) { sh[w] = s; sh[4 + w] = s2; }
    __syncthreads();
    float ts  = sh[0] + sh[1] + sh[2] + sh[3];
    float ts2 = sh[4] + sh[5] + sh[6] + sh[7];
    float mean = ts * (1.f / 128.f);
    float var  = ts2 * (1.f / 128.f) - mean * mean;
    g_h[row * Dd + tid] = (v - mean) * rsqrtf(var + 1e-5f) * g[tid] + b[tid];
}

// ======================= body GEMM (round-4 proven) =======================
__global__ __launch_bounds__(256)
void gemm64_kernel(int asel, const float* __restrict__ Bext, int bofs,
                   const float* __restrict__ bias, int use_res, int csel,
                   int N, int K, int relu) {
    __shared__ float As[32][65];
    __shared__ __align__(16) float Bs[32][64];
    const float* A = buf_sel(asel);
    float* C = buf_sel(csel);
    const float* Bm = Bext ? Bext : (g_wqkv + bofs);
    int tid = threadIdx.x;
    int tx = tid & 15, ty = tid >> 4;
    int r0 = blockIdx.y * 64, c0 = blockIdx.x * 64;
    int ar = tid >> 3, ak = (tid & 7) * 4;
    int br = tid >> 4, bc = (tid & 15) * 4;
    float acc[4][4] = {};
    for (int k0 = 0; k0 < K; k0 += 32) {
        float4 a0 = *(const float4*)&A[(size_t)(r0 + ar)      * K + k0 + ak];
        float4 a1 = *(const float4*)&A[(size_t)(r0 + ar + 32) * K + k0 + ak];
        As[ak + 0][ar] = a0.x; As[ak + 1][ar] = a0.y;
        As[ak + 2][ar] = a0.z; As[ak + 3][ar] = a0.w;
        As[ak + 0][ar + 32] = a1.x; As[ak + 1][ar + 32] = a1.y;
        As[ak + 2][ar + 32] = a1.z; As[ak + 3][ar + 32] = a1.w;
        *(float4*)&Bs[br][bc]      = *(const float4*)&Bm[(size_t)(k0 + br)      * N + c0 + bc];
        *(float4*)&Bs[br + 16][bc] = *(const float4*)&Bm[(size_t)(k0 + br + 16) * N + c0 + bc];
        __syncthreads();
        #pragma unroll
        for (int kk = 0; kk < 32; kk++) {
            float4 bv = *(const float4*)&Bs[kk][tx * 4];
            float a0r = As[kk][ty * 4 + 0];
            float a1r = As[kk][ty * 4 + 1];
            float a2r = As[kk][ty * 4 + 2];
            float a3r = As[kk][ty * 4 + 3];
            acc[0][0] += a0r * bv.x; acc[0][1] += a0r * bv.y; acc[0][2] += a0r * bv.z; acc[0][3] += a0r * bv.w;
            acc[1][0] += a1r * bv.x; acc[1][1] += a1r * bv.y; acc[1][2] += a1r * bv.z; acc[1][3] += a1r * bv.w;
            acc[2][0] += a2r * bv.x; acc[2][1] += a2r * bv.y; acc[2][2] += a2r * bv.z; acc[2][3] += a2r * bv.w;
            acc[3][0] += a3r * bv.x; acc[3][1] += a3r * bv.y; acc[3][2] += a3r * bv.z; acc[3][3] += a3r * bv.w;
        }
        __syncthreads();
    }
    #pragma unroll
    for (int i = 0; i < 4; i++) {
        int rr = r0 + ty * 4 + i;
        #pragma unroll
        for (int j = 0; j < 4; j++) {
            int cc = c0 + tx * 4 + j;
            float v = acc[i][j];
            if (bias) v += bias[cc];
            if (relu) v = fmaxf(v, 0.f);
            if (use_res) v += g_x[(size_t)rr * N + cc];
            C[(size_t)rr * N + cc] = v;
        }
    }
}

// ======================= attention (round-4 proven) =======================
__global__ void attn_kernel() {
    __shared__ float k_s[16][129];
    __shared__ float v_s[16][129];
    __shared__ float p_s[4][128];
    int bh = blockIdx.x;
    int b = bh >> 3, h = bh & 7;
    int tid = threadIdx.x;
    int w = tid >> 5, lane = tid & 31;
    int base_bt = b * Tt;
    for (int i = tid; i < Tt * HDh; i += 128) {
        int s = i >> 4, e = i & 15;
        size_t g = (size_t)(base_bt + s) * 384 + h * HDh + e;
        k_s[e][s] = g_qkv[g + 128];
        v_s[e][s] = g_qkv[g + 256];
    }
    __syncthreads();
    const float scale = 0.08838834764831845f;
    for (int t = w; t < Tt; t += 4) {
        float q[16];
        size_t qg = (size_t)(base_bt + t) * 384 + h * HDh;
        #pragma unroll
        for (int e = 0; e < 16; e++) q[e] = g_qkv[qg + e];
        float sc[4];
        #pragma unroll
        for (int j = 0; j < 4; j++) {
            int s = lane + 32 * j;
            float dot = 0.f;
            #pragma unroll
            for (int e = 0; e < 16; e++) dot += q[e] * k_s[e][s];
            sc[j] = (s <= t) ? dot * scale : -1e30f;
        }
        float m = fmaxf(fmaxf(sc[0], sc[1]), fmaxf(sc[2], sc[3]));
        #pragma unroll
        for (int o = 16; o; o >>= 1) m = fmaxf(m, __shfl_xor_sync(0xffffffffu, m, o));
        float p[4], ps = 0.f;
        #pragma unroll
        for (int j = 0; j < 4; j++) {
            int s = lane + 32 * j;
            p[j] = (s <= t) ? __expf(sc[j] - m) : 0.f;
            ps += p[j];
        }
        #pragma unroll
        for (int o = 16; o; o >>= 1) ps += __shfl_xor_sync(0xffffffffu, ps, o);
        float inv = 1.f / ps;
        #pragma unroll
        for (int j = 0; j < 4; j++) p_s[w][lane + 32 * j] = p[j] * inv;
        __syncwarp();
        int e = lane & 15, half = lane >> 4;
        float acc = 0.f;
        int sb = half * 64;
        #pragma unroll
        for (int s = 0; s < 64; s++) acc += p_s[w][sb + s] * v_s[e][sb + s];
        acc += __shfl_xor_sync(0xffffffffu, acc, 16);
        if (lane < 16) g_att[(size_t)(base_bt + t) * Dd + h * HDh + e] = acc;
        __syncwarp();
    }
}

// ======================= LM head (HMMA, fragment-reuse mainloop) =======================
constexpr int LMS = 264;  // row stride in bf16 elems

__global__ __launch_bounds__(256, 2)
void lmhead_hmma(const float* __restrict__ lmb, float* __restrict__ out) {
    extern __shared__ __nv_bfloat16 sm[];
    __nv_bfloat16* As = sm;               // 128 x LMS
    __nv_bfloat16* Bs = sm + 128 * LMS;   // 64 x LMS
    int tid = threadIdx.x;
    int m0 = blockIdx.x * 128, n0 = blockIdx.y * 64;

    #pragma unroll
    for (int i = 0; i < 16; i++) {
        int idx = tid + i * 256;
        int r = idx >> 5, u = idx & 31;
        uint4 v = *(const uint4*)&g_hb[((size_t)(m0 + r)) * 256 + u * 8];
        *(uint4*)&As[r * LMS + u * 8] = v;
    }
    #pragma unroll
    for (int i = 0; i < 8; i++) {
        int idx = tid + i * 256;
        int r = idx >> 5, u = idx & 31;
        uint4 v = *(const uint4*)&g_lmwb[((size_t)(n0 + r)) * 256 + u * 8];
        *(uint4*)&Bs[r * LMS + u * 8] = v;
    }
    __syncthreads();

    int wid = tid >> 5, lane = tid & 31;
    int wm = (wid & 3) * 32;     // warp m offset
    int wn = (wid >> 2) * 32;    // warp n offset

    // A ldmatrix x4 bases (2 x m16 frags)
    uint32_t a_base[2];
    #pragma unroll
    for (int i = 0; i < 2; i++) {
        int row = wm + i * 16 + (lane & 15);
        int col = (lane >> 4) * 8;
        a_base[i] = smem_u32(&As[row * LMS + col]);
    }
    // B ldmatrix x4 bases: one x4 load gives frags for two adjacent n8 tiles
    uint32_t b_base4[2];
    #pragma unroll
    for (int jj = 0; jj < 2; jj++) {
        int row = wn + jj * 16 + ((lane >> 4) & 1) * 8 + (lane & 7);
        int col = ((lane >> 3) & 1) * 8;
        b_base4[jj] = smem_u32(&Bs[row * LMS + col]);
    }

    float acc[2][4][4];
    #pragma unroll
    for (int i = 0; i < 2; i++)
        #pragma unroll
        for (int j = 0; j < 4; j++)
            #pragma unroll
            for (int q = 0; q < 4; q++) acc[i][j][q] = 0.f;

#define MMA_GRP(AF, BF)                                                           \
    _Pragma("unroll")                                                             \
    for (int i = 0; i < 2; i++)                                                   \
        _Pragma("unroll")                                                         \
        for (int j = 0; j < 4; j++)                                               \
            asm volatile(                                                         \
                "mma.sync.aligned.m16n8k16.row.col.f32.bf16.bf16.f32 "            \
                "{%0,%1,%2,%3}, {%4,%5,%6,%7}, {%8,%9}, {%0,%1,%2,%3};"           \
                : "+f"(acc[i][j][0]), "+f"(acc[i][j][1]),                         \
                  "+f"(acc[i][j][2]), "+f"(acc[i][j][3])                          \
                : "r"(AF[i][0]), "r"(AF[i][1]), "r"(AF[i][2]), "r"(AF[i][3]),     \
                  "r"(BF[j][0]), "r"(BF[j][1]));

    // fragment-reuse mainloop: 8 LDSM per k-step (was 18), same 24 MMAs
    #pragma unroll
    for (int ks = 0; ks < 8; ks++) {
        int ofs = ks * 32;
        uint32_t a_hi[2][4], a_lo[2][4], b_hi[4][2], b_lo[4][2];
        #pragma unroll
        for (int i = 0; i < 2; i++)
            asm volatile("ldmatrix.sync.aligned.m8n8.x4.shared.b16 {%0,%1,%2,%3}, [%4];"
                         : "=r"(a_hi[i][0]), "=r"(a_hi[i][1]), "=r"(a_hi[i][2]), "=r"(a_hi[i][3])
                         : "r"(a_base[i] + ofs));
        #pragma unroll
        for (int jj = 0; jj < 2; jj++)
            asm volatile("ldmatrix.sync.aligned.m8n8.x4.shared.b16 {%0,%1,%2,%3}, [%4];"
                         : "=r"(b_hi[2 * jj][0]), "=r"(b_hi[2 * jj][1]),
                           "=r"(b_hi[2 * jj + 1][0]), "=r"(b_hi[2 * jj + 1][1])
                         : "r"(b_base4[jj] + ofs));
        MMA_GRP(a_hi, b_hi)                                  // Ah * Bh
        #pragma unroll
        for (int i = 0; i < 2; i++)
            asm volatile("ldmatrix.sync.aligned.m8n8.x4.shared.b16 {%0,%1,%2,%3}, [%4];"
                         : "=r"(a_lo[i][0]), "=r"(a_lo[i][1]), "=r"(a_lo[i][2]), "=r"(a_lo[i][3])
                         : "r"(a_base[i] + 256 + ofs));
        MMA_GRP(a_lo, b_hi)                                  // Al * Bh
        #pragma unroll
        for (int jj = 0; jj < 2; jj++)
            asm volatile("ldmatrix.sync.aligned.m8n8.x4.shared.b16 {%0,%1,%2,%3}, [%4];"
                         : "=r"(b_lo[2 * jj][0]), "=r"(b_lo[2 * jj][1]),
                           "=r"(b_lo[2 * jj + 1][0]), "=r"(b_lo[2 * jj + 1][1])
                         : "r"(b_base4[jj] + 256 + ofs));
        MMA_GRP(a_hi, b_lo)                                  // Ah * Bl
    }
#undef MMA_GRP

    float bias0[4], bias1[4];
    #pragma unroll
    for (int j = 0; j < 4; j++) {
        int c = n0 + wn + j * 8 + (lane & 3) * 2;
        bias0[j] = (c < Vv) ? lmb[c] : 0.f;
        bias1[j] = (c + 1 < Vv) ? lmb[c + 1] : 0.f;
    }

    #pragma unroll
    for (int i = 0; i < 2; i++) {
        #pragma unroll
        for (int hf = 0; hf < 2; hf++) {
            int row = m0 + wm + i * 16 + (lane >> 2) + hf * 8;
            size_t ro = (size_t)row * Vv;
            float rexp = 0.f;
            #pragma unroll
            for (int j = 0; j < 4; j++) {
                int c = n0 + wn + j * 8 + (lane & 3) * 2;
                float v0 = acc[i][j][hf * 2]     + bias0[j];
                float v1 = acc[i][j][hf * 2 + 1] + bias1[j];
                if (c < Vv) {
                    if (out) out[ro + c] = v0;
                    rexp += __expf(v0);
                }
                if (c + 1 < Vv) {
                    if (out) out[ro + c + 1] = v1;
                    rexp += __expf(v1);
                }
            }
            rexp += __shfl_xor_sync(0xffffffffu, rexp, 1);
            rexp += __shfl_xor_sync(0xffffffffu, rexp, 2);
            if ((lane & 3) == 0) atomicAdd(&g_rowsum[row], rexp);
        }
    }
}

// ======================= loss =======================
__global__ void rownll_kernel(const int* __restrict__ targets,
                              const float* __restrict__ lm_w,
                              const float* __restrict__ lmb) {
    int gw = (blockIdx.x * blockDim.x + threadIdx.x) >> 5;
    int lane = threadIdx.x & 31;
    for (int r = gw; r < BT; r += 512) {
        int tgt = targets[r];
        float dot = 0.f;
        const float* xr = &g_h[(size_t)r * Dd];
        #pragma unroll
        for (int i = 0; i < 4; i++) {
            int d = lane + 32 * i;
            dot += xr[d] * lm_w[(size_t)d * Vv + tgt];
        }
        #pragma unroll
        for (int o = 16; o; o >>= 1) dot += __shfl_xor_sync(0xffffffffu, dot, o);
        if (lane == 0) g_att[r] = logf(g_rowsum[r]) - (dot + lmb[tgt]);
    }
}

__global__ void lossred_kernel(float* __restrict__ loss_out) {
    int tid = threadIdx.x;
    float local = 0.f;
    for (int r = tid; r < BT; r += 1024) local += g_att[r];
    #pragma unroll
    for (int o = 16; o; o >>= 1) local += __shfl_xor_sync(0xffffffffu, local, o);
    __shared__ float red[32];
    if ((tid & 31) == 0) red[tid >> 5] = local;
    __syncthreads();
    if (tid < 32) {
        float v = red[tid];
        #pragma unroll
        for (int o = 16; o; o >>= 1) v += __shfl_xor_sync(0xffffffffu, v, o);
        if (tid == 0 && loss_out) *loss_out = v * (1.f / (float)BT);
    }
}

// ======================= launch =======================
extern "C" void kernel_launch(void* const* d_in, const int* in_sizes, int n_in,
                              void* d_out, int out_size) {
    const int*   idx     = (const int*)  d_in[0];
    const int*   targets = (const int*)  d_in[1];
    const float* tok_emb = (const float*)d_in[2];
    const float* pos_emb = (const float*)d_in[3];
    const float* wq      = (const float*)d_in[4];
    const float* wk      = (const float*)d_in[5];
    const float* wv      = (const float*)d_in[6];
    const float* wproj   = (const float*)d_in[7];
    const float* bproj   = (const float*)d_in[8];
    const float* w1      = (const float*)d_in[9];
    const float* b1      = (const float*)d_in[10];
    const float* w2      = (const float*)d_in[11];
    const float* b2      = (const float*)d_in[12];
    const float* ln1_g   = (const float*)d_in[13];
    const float* ln1_b   = (const float*)d_in[14];
    const float* ln2_g   = (const float*)d_in[15];
    const float* ln2_b   = (const float*)d_in[16];
    const float* lnf_g   = (const float*)d_in[17];
    const float* lnf_b   = (const float*)d_in[18];
    const float* lm_w    = (const float*)d_in[19];
    const float* lm_b    = (const float*)d_in[20];

    float* outf = (float*)d_out;
    long long btv = (long long)BT * Vv;
    float* logits = ((long long)out_size >= btv) ? outf : nullptr;
    float* lossp  = nullptr;
    if ((long long)out_size == btv + 1) lossp = outf + btv;
    else if ((long long)out_size < btv && out_size >= 1) lossp = outf + (out_size - 1);

    constexpr int LM_SMEM = (128 * LMS + 64 * LMS) * 2;  // 101376
    cudaFuncSetAttribute(lmhead_hmma, cudaFuncAttributeMaxDynamicSharedMemorySize, LM_SMEM);

    prep_kernel<<<256, 256>>>(wq, wk, wv);
    convw_kernel<<<dim3(VP / 32, 4), dim3(32, 8)>>>(lm_w);
    embed_kernel<<<BT, 128>>>(idx, tok_emb, pos_emb);

    for (int l = 0; l < Ll; l++) {
        ln_kernel<<<BT, 128>>>(ln1_g + l * Dd, ln1_b + l * Dd);
        gemm64_kernel<<<dim3(384 / 64, BT / 64), 256>>>(
            1, nullptr, l * Dd * 384, nullptr, 0, 2, 384, 128, 0);
        attn_kernel<<<Bb * Hh, 128>>>();
        gemm64_kernel<<<dim3(128 / 64, BT / 64), 256>>>(
            3, wproj + (size_t)l * Dd * Dd, 0, bproj + l * Dd, 1, 0, 128, 128, 0);
        ln_kernel<<<BT, 128>>>(ln2_g + l * Dd, ln2_b + l * Dd);
        gemm64_kernel<<<dim3(512 / 64, BT / 64), 256>>>(
            1, w1 + (size_t)l * Dd * 4 * Dd, 0, b1 + l * 4 * Dd, 0, 4, 512, 128, 1);
        gemm64_kernel<<<dim3(128 / 64, BT / 64), 256>>>(
            4, w2 + (size_t)l * 4 * Dd * Dd, 0, b2 + l * Dd, 1, 0, 128, 512, 0);
    }
    ln_kernel<<<BT, 128>>>(lnf_g, lnf_b);
    convh_kernel<<<(BT * Dd + 255) / 256, 256>>>();
    lmhead_hmma<<<dim3(BT / 128, VP / 64), 256, LM_SMEM>>>(lm_b, logits);
    rownll_kernel<<<64, 256>>>(targets, lm_w, lm_b);
    lossred_kernel<<<1, 1024>>>(lossp);
}